// round 1
// baseline (speedup 1.0000x reference)
#include <cuda_runtime.h>

// Dice loss: pred (2,8,128^3) fp32, ref (2,1,128^3) int32 -> scalar fp32.
// Pass 1: streaming kernel, per-voxel argmax over 8 channels, warp-reduced
//         per-class {inter, psum, rsum} counts, per-block partials to scratch.
// Pass 2: single-block reduction + dice math -> out[0].

#define S_VOX (128*128*128)          // 2097152 voxels per batch item
#define CNUM 8
#define BNUM 2
#define TPB 256
#define VPT 4                         // voxels per thread (float4)
#define VOX_PER_BLOCK (TPB*VPT)       // 1024
#define BLOCKS_PER_B (S_VOX / VOX_PER_BLOCK)   // 2048
#define NBLOCKS (BNUM * BLOCKS_PER_B)          // 4096
#define NCNT 21                        // 7 classes x {inter,psum,rsum}

__device__ int g_partials[NBLOCKS * NCNT];

__global__ __launch_bounds__(TPB) void dice_count_kernel(
    const float* __restrict__ pred, const int* __restrict__ ref)
{
    __shared__ int s_cnt[NCNT];
    const int tid = threadIdx.x;
    if (tid < NCNT) s_cnt[tid] = 0;
    __syncthreads();

    const int blk  = blockIdx.x;
    const int b    = blk / BLOCKS_PER_B;                 // batch index (const per block)
    const int sIdx = (blk % BLOCKS_PER_B) * VOX_PER_BLOCK + tid * VPT;

    // 8 channel loads, each float4 (16B), all coalesced, issued back-to-back for MLP.
    const float4* pbase = (const float4*)(pred + (size_t)b * CNUM * S_VOX + sIdx);
    float4 v[CNUM];
    #pragma unroll
    for (int c = 0; c < CNUM; ++c)
        v[c] = pbase[(size_t)c * (S_VOX / 4)];

    const int4 r = *(const int4*)(ref + (size_t)b * S_VOX + sIdx);

    // argmax per voxel slot (first-max semantics, matches jnp.argmax)
    int p0 = 0, p1 = 0, p2 = 0, p3 = 0;
    float m0 = v[0].x, m1 = v[0].y, m2 = v[0].z, m3 = v[0].w;
    #pragma unroll
    for (int c = 1; c < CNUM; ++c) {
        if (v[c].x > m0) { m0 = v[c].x; p0 = c; }
        if (v[c].y > m1) { m1 = v[c].y; p1 = c; }
        if (v[c].z > m2) { m2 = v[c].z; p2 = c; }
        if (v[c].w > m3) { m3 = v[c].w; p3 = c; }
    }

    const int lane = tid & 31;
    #pragma unroll
    for (int cls = 1; cls < CNUM; ++cls) {
        int lp = (p0==cls) + (p1==cls) + (p2==cls) + (p3==cls);
        int lr = (r.x==cls) + (r.y==cls) + (r.z==cls) + (r.w==cls);
        int li = ((p0==cls)&(r.x==cls)) + ((p1==cls)&(r.y==cls))
               + ((p2==cls)&(r.z==cls)) + ((p3==cls)&(r.w==cls));
        lp = (int)__reduce_add_sync(0xffffffffu, (unsigned)lp);
        lr = (int)__reduce_add_sync(0xffffffffu, (unsigned)lr);
        li = (int)__reduce_add_sync(0xffffffffu, (unsigned)li);
        if (lane == 0) {
            const int j = (cls - 1) * 3;
            atomicAdd(&s_cnt[j + 0], li);
            atomicAdd(&s_cnt[j + 1], lp);
            atomicAdd(&s_cnt[j + 2], lr);
        }
    }
    __syncthreads();
    if (tid < NCNT) g_partials[blk * NCNT + tid] = s_cnt[tid];
}

__global__ __launch_bounds__(1024) void dice_final_kernel(float* __restrict__ out)
{
    __shared__ int s_tot[BNUM * NCNT];
    const int tid = threadIdx.x;
    if (tid < BNUM * NCNT) s_tot[tid] = 0;
    __syncthreads();

    // 4096 rows / 1024 threads = 4 rows per thread: rows tid, tid+1024 are b=0;
    // rows tid+2048, tid+3072 are b=1. Static indexing -> no local-mem spill.
    int acc0[NCNT], acc1[NCNT];
    #pragma unroll
    for (int j = 0; j < NCNT; ++j) { acc0[j] = 0; acc1[j] = 0; }

    #pragma unroll
    for (int k = 0; k < 2; ++k) {
        const int row_a = tid + k * 1024;          // b = 0
        const int row_b = tid + 2048 + k * 1024;   // b = 1
        #pragma unroll
        for (int j = 0; j < NCNT; ++j) {
            acc0[j] += g_partials[row_a * NCNT + j];
            acc1[j] += g_partials[row_b * NCNT + j];
        }
    }

    const int lane = tid & 31;
    #pragma unroll
    for (int j = 0; j < NCNT; ++j) {
        int v0 = (int)__reduce_add_sync(0xffffffffu, (unsigned)acc0[j]);
        int v1 = (int)__reduce_add_sync(0xffffffffu, (unsigned)acc1[j]);
        if (lane == 0) {
            if (v0) atomicAdd(&s_tot[j], v0);
            if (v1) atomicAdd(&s_tot[NCNT + j], v1);
        }
    }
    __syncthreads();

    if (tid == 0) {
        float lsum = 0.0f;
        #pragma unroll
        for (int b = 0; b < BNUM; ++b) {
            float dsum = 0.0f, w = 0.0f;
            #pragma unroll
            for (int c = 0; c < CNUM - 1; ++c) {
                const float inter = (float)s_tot[b * NCNT + c * 3 + 0];
                const float psum  = (float)s_tot[b * NCNT + c * 3 + 1];
                const float rsum  = (float)s_tot[b * NCNT + c * 3 + 2];
                if (rsum > 0.0f) {
                    const float uni = psum + rsum;
                    dsum += 2.0f * inter / (uni > 0.0f ? uni : 1.0f);
                    w += 1.0f;
                }
            }
            lsum += dsum / w;   // w >= 1 whenever any class present; matches ref
        }
        out[0] = lsum / (float)BNUM;
    }
}

extern "C" void kernel_launch(void* const* d_in, const int* in_sizes, int n_in,
                              void* d_out, int out_size)
{
    const float* pred = (const float*)d_in[0];
    const int*   ref  = (const int*)d_in[1];
    float*       out  = (float*)d_out;

    dice_count_kernel<<<NBLOCKS, TPB>>>(pred, ref);
    dice_final_kernel<<<1, 1024>>>(out);
}

// round 2
// speedup vs baseline: 1.5208x; 1.5208x over previous
#include <cuda_runtime.h>

// Dice loss: pred (2,8,128^3) fp32, ref (2,1,128^3) int32 -> scalar fp32.
// Single fused kernel: streaming per-voxel argmax + packed per-thread counting,
// block reduction -> 42 global int counters, last-block (ticket) finalize.

#define S_VOX (128*128*128)            // 2097152 voxels per batch
#define GROUPS_PER_B (S_VOX / 4)       // 524288 float4-groups per batch
#define CNUM 8
#define BNUM 2
#define TPB 256
#define NBLK 1024
#define BLOCKS_PER_B (NBLK / BNUM)     // 512
#define GROUPS_PER_BLK (GROUPS_PER_B / BLOCKS_PER_B)   // 1024
#define ITERS (GROUPS_PER_BLK / TPB)   // 4 iterations (16 voxels/thread)
#define NCNT 21                        // 7 classes x {inter,psum,rsum}

__device__ int g_cnt[BNUM * 24];       // [b][ (cls-1)*3 + k ], 24-padded
__device__ unsigned int g_ticket;

__global__ __launch_bounds__(TPB) void dice_fused_kernel(
    const float* __restrict__ pred, const int* __restrict__ ref,
    float* __restrict__ out)
{
    __shared__ int s_cnt[NCNT];
    const int tid = threadIdx.x;
    if (tid < NCNT) s_cnt[tid] = 0;
    __syncthreads();

    const int blk   = blockIdx.x;
    const int b     = blk >> 9;                    // blk / BLOCKS_PER_B
    const int local = blk & (BLOCKS_PER_B - 1);
    const int gBase = local * GROUPS_PER_BLK;

    const float4* pbase = (const float4*)pred + (size_t)b * CNUM * GROUPS_PER_B;
    const int4*   rbase = (const int4*)ref   + (size_t)b * GROUPS_PER_B;

    // Packed per-thread accumulators: 8 classes x 8-bit counts.
    unsigned long long pac = 0ULL, rac = 0ULL, iac = 0ULL;

    #pragma unroll
    for (int it = 0; it < ITERS; ++it) {
        const int g = gBase + it * TPB + tid;

        // 9 back-to-back loads: 8 channel float4 + 1 ref int4 (MLP=9)
        float4 v[CNUM];
        #pragma unroll
        for (int c = 0; c < CNUM; ++c)
            v[c] = pbase[(size_t)c * GROUPS_PER_B + g];
        const int4 r = rbase[g];

        // argmax per voxel slot (first-max semantics == jnp.argmax)
        int p0 = 0, p1 = 0, p2 = 0, p3 = 0;
        float m0 = v[0].x, m1 = v[0].y, m2 = v[0].z, m3 = v[0].w;
        #pragma unroll
        for (int c = 1; c < CNUM; ++c) {
            if (v[c].x > m0) { m0 = v[c].x; p0 = c; }
            if (v[c].y > m1) { m1 = v[c].y; p1 = c; }
            if (v[c].z > m2) { m2 = v[c].z; p2 = c; }
            if (v[c].w > m3) { m3 = v[c].w; p3 = c; }
        }

        // Packed counting: one 64-bit add per count.
        {
            unsigned long long bp = 1ULL << (p0 << 3);
            pac += bp; if (p0 == r.x) iac += bp;
            rac += 1ULL << (r.x << 3);
        }
        {
            unsigned long long bp = 1ULL << (p1 << 3);
            pac += bp; if (p1 == r.y) iac += bp;
            rac += 1ULL << (r.y << 3);
        }
        {
            unsigned long long bp = 1ULL << (p2 << 3);
            pac += bp; if (p2 == r.z) iac += bp;
            rac += 1ULL << (r.z << 3);
        }
        {
            unsigned long long bp = 1ULL << (p3 << 3);
            pac += bp; if (p3 == r.w) iac += bp;
            rac += 1ULL << (r.w << 3);
        }
    }

    // Unpack classes 1..7 and warp-reduce (constant shifts -> cheap).
    const int lane = tid & 31;
    #pragma unroll
    for (int cls = 1; cls < CNUM; ++cls) {
        int li = (int)((iac >> (cls * 8)) & 0xFF);
        int lp = (int)((pac >> (cls * 8)) & 0xFF);
        int lr = (int)((rac >> (cls * 8)) & 0xFF);
        li = (int)__reduce_add_sync(0xffffffffu, (unsigned)li);
        lp = (int)__reduce_add_sync(0xffffffffu, (unsigned)lp);
        lr = (int)__reduce_add_sync(0xffffffffu, (unsigned)lr);
        if (lane == 0) {
            const int j = (cls - 1) * 3;
            atomicAdd(&s_cnt[j + 0], li);
            atomicAdd(&s_cnt[j + 1], lp);
            atomicAdd(&s_cnt[j + 2], lr);
        }
    }
    __syncthreads();

    if (tid < NCNT) atomicAdd(&g_cnt[b * 24 + tid], s_cnt[tid]);
    __syncthreads();

    // Last-block finalize (threadfence-reduction pattern).
    if (tid == 0) {
        __threadfence();
        unsigned int t = atomicAdd(&g_ticket, 1u);
        if (t == (unsigned)(NBLK - 1)) {
            float lsum = 0.0f;
            #pragma unroll
            for (int bb = 0; bb < BNUM; ++bb) {
                float dsum = 0.0f, w = 0.0f;
                #pragma unroll
                for (int c = 0; c < CNUM - 1; ++c) {
                    const float inter = (float)atomicAdd(&g_cnt[bb * 24 + c * 3 + 0], 0);
                    const float psum  = (float)atomicAdd(&g_cnt[bb * 24 + c * 3 + 1], 0);
                    const float rsum  = (float)atomicAdd(&g_cnt[bb * 24 + c * 3 + 2], 0);
                    if (rsum > 0.0f) {
                        const float uni = psum + rsum;
                        dsum += 2.0f * inter / (uni > 0.0f ? uni : 1.0f);
                        w += 1.0f;
                    }
                }
                lsum += dsum / w;
            }
            out[0] = lsum / (float)BNUM;

            // Reset state for the next graph replay (deterministic).
            #pragma unroll
            for (int i = 0; i < BNUM * 24; ++i) atomicExch(&g_cnt[i], 0);
            atomicExch(&g_ticket, 0u);
        }
    }
}

extern "C" void kernel_launch(void* const* d_in, const int* in_sizes, int n_in,
                              void* d_out, int out_size)
{
    const float* pred = (const float*)d_in[0];
    const int*   ref  = (const int*)d_in[1];
    float*       out  = (float*)d_out;

    dice_fused_kernel<<<NBLK, TPB>>>(pred, ref, out);
}

// round 3
// speedup vs baseline: 1.6144x; 1.0615x over previous
#include <cuda_runtime.h>

// Dice loss: pred (2,8,128^3) fp32, ref (2,1,128^3) int32 -> scalar fp32.
// Persistent single-wave kernel: 444 blocks (148 SM x 3), grid-stride tiles,
// per-voxel argmax, packed 8-bit per-thread class counts, block reduction ->
// 42 global counters, last-block ticket finalize.

#define S_VOX (128*128*128)            // 2097152 voxels per batch
#define GROUPS_PER_B (S_VOX / 4)       // 524288 float4-groups per batch
#define CNUM 8
#define BNUM 2
#define TPB 256
#define NBLK 444                       // 148 SMs x 3 blocks
#define HALF (NBLK / 2)                // 222 blocks per batch
#define TILES_PER_B (GROUPS_PER_B / TPB)   // 2048 tiles of 256 groups
#define NCNT 21                        // 7 classes x {inter,psum,rsum}

__device__ int g_cnt[BNUM * 24];
__device__ unsigned int g_ticket;

__global__ __launch_bounds__(TPB, 3) void dice_fused_kernel(
    const float* __restrict__ pred, const int* __restrict__ ref,
    float* __restrict__ out)
{
    __shared__ int s_cnt[NCNT];
    const int tid = threadIdx.x;
    if (tid < NCNT) s_cnt[tid] = 0;
    __syncthreads();

    const int blk = blockIdx.x;
    const int b   = (blk >= HALF) ? 1 : 0;
    const int lb  = b ? (blk - HALF) : blk;

    const float4* pbase = (const float4*)pred + (size_t)b * CNUM * GROUPS_PER_B;
    const int4*   rbase = (const int4*)ref   + (size_t)b * GROUPS_PER_B;

    // Packed per-thread accumulators: 8 classes x 8-bit counts (max 40 each).
    unsigned long long pac = 0ULL, rac = 0ULL, iac = 0ULL;

    for (int t = lb; t < TILES_PER_B; t += HALF) {
        const int g = t * TPB + tid;

        // 9 back-to-back streaming loads (evict-first): MLP = 9.
        float4 v[CNUM];
        #pragma unroll
        for (int c = 0; c < CNUM; ++c)
            v[c] = __ldcs(&pbase[(size_t)c * GROUPS_PER_B + g]);
        const int4 r = __ldcs(&rbase[g]);

        // argmax per voxel slot (first-max semantics == jnp.argmax)
        int p0 = 0, p1 = 0, p2 = 0, p3 = 0;
        float m0 = v[0].x, m1 = v[0].y, m2 = v[0].z, m3 = v[0].w;
        #pragma unroll
        for (int c = 1; c < CNUM; ++c) {
            if (v[c].x > m0) { m0 = v[c].x; p0 = c; }
            if (v[c].y > m1) { m1 = v[c].y; p1 = c; }
            if (v[c].z > m2) { m2 = v[c].z; p2 = c; }
            if (v[c].w > m3) { m3 = v[c].w; p3 = c; }
        }

        // Packed counting: one 64-bit add per count.
        {
            unsigned long long bp = 1ULL << (p0 << 3);
            pac += bp; if (p0 == r.x) iac += bp;
            rac += 1ULL << (r.x << 3);
        }
        {
            unsigned long long bp = 1ULL << (p1 << 3);
            pac += bp; if (p1 == r.y) iac += bp;
            rac += 1ULL << (r.y << 3);
        }
        {
            unsigned long long bp = 1ULL << (p2 << 3);
            pac += bp; if (p2 == r.z) iac += bp;
            rac += 1ULL << (r.z << 3);
        }
        {
            unsigned long long bp = 1ULL << (p3 << 3);
            pac += bp; if (p3 == r.w) iac += bp;
            rac += 1ULL << (r.w << 3);
        }
    }

    // Unpack classes 1..7 and warp-reduce (constant shifts -> cheap).
    const int lane = tid & 31;
    #pragma unroll
    for (int cls = 1; cls < CNUM; ++cls) {
        int li = (int)((iac >> (cls * 8)) & 0xFF);
        int lp = (int)((pac >> (cls * 8)) & 0xFF);
        int lr = (int)((rac >> (cls * 8)) & 0xFF);
        li = (int)__reduce_add_sync(0xffffffffu, (unsigned)li);
        lp = (int)__reduce_add_sync(0xffffffffu, (unsigned)lp);
        lr = (int)__reduce_add_sync(0xffffffffu, (unsigned)lr);
        if (lane == 0) {
            const int j = (cls - 1) * 3;
            atomicAdd(&s_cnt[j + 0], li);
            atomicAdd(&s_cnt[j + 1], lp);
            atomicAdd(&s_cnt[j + 2], lr);
        }
    }
    __syncthreads();

    if (tid < NCNT) atomicAdd(&g_cnt[b * 24 + tid], s_cnt[tid]);
    __syncthreads();

    // Last-block finalize (threadfence-reduction pattern).
    if (tid == 0) {
        __threadfence();
        unsigned int t = atomicAdd(&g_ticket, 1u);
        if (t == (unsigned)(NBLK - 1)) {
            float lsum = 0.0f;
            #pragma unroll
            for (int bb = 0; bb < BNUM; ++bb) {
                float dsum = 0.0f, w = 0.0f;
                #pragma unroll
                for (int c = 0; c < CNUM - 1; ++c) {
                    const float inter = (float)atomicAdd(&g_cnt[bb * 24 + c * 3 + 0], 0);
                    const float psum  = (float)atomicAdd(&g_cnt[bb * 24 + c * 3 + 1], 0);
                    const float rsum  = (float)atomicAdd(&g_cnt[bb * 24 + c * 3 + 2], 0);
                    if (rsum > 0.0f) {
                        const float uni = psum + rsum;
                        dsum += 2.0f * inter / (uni > 0.0f ? uni : 1.0f);
                        w += 1.0f;
                    }
                }
                lsum += dsum / w;
            }
            out[0] = lsum / (float)BNUM;

            // Reset state for the next graph replay (deterministic).
            #pragma unroll
            for (int i = 0; i < BNUM * 24; ++i) atomicExch(&g_cnt[i], 0);
            atomicExch(&g_ticket, 0u);
        }
    }
}

extern "C" void kernel_launch(void* const* d_in, const int* in_sizes, int n_in,
                              void* d_out, int out_size)
{
    const float* pred = (const float*)d_in[0];
    const int*   ref  = (const int*)d_in[1];
    float*       out  = (float*)d_out;

    dice_fused_kernel<<<NBLK, TPB>>>(pred, ref, out);
}